// round 1
// baseline (speedup 1.0000x reference)
#include <cuda_runtime.h>

#define N_RAYS   8192
#define P        256
#define HID      64
#define OUTW     261   // 3 rgb + depth + missed + 256 probs

// ---------- packed f32x2 helpers (Blackwell FFMA2 via PTX) ----------
__device__ __forceinline__ unsigned long long pack2(float x, float y) {
    unsigned long long r;
    asm("mov.b64 %0, {%1, %2};" : "=l"(r) : "f"(x), "f"(y));
    return r;
}
__device__ __forceinline__ void unpack2(unsigned long long a, float& x, float& y) {
    asm("mov.b64 {%0, %1}, %2;" : "=f"(x), "=f"(y) : "l"(a));
}
__device__ __forceinline__ unsigned long long fma2(unsigned long long a,
                                                   unsigned long long b,
                                                   unsigned long long c) {
    unsigned long long d;
    asm("fma.rn.f32x2 %0, %1, %2, %3;" : "=l"(d) : "l"(a), "l"(b), "l"(c));
    return d;
}

__global__ __launch_bounds__(256) void vr_kernel(
    const float* __restrict__ ray_start,   // [N,3]
    const float* __restrict__ ray_dir,     // [N,3]
    const float* __restrict__ depth,       // [N,P]
    const float* __restrict__ dists,       // [N,P]
    const int*   __restrict__ sidx,        // [N,P] (int32; only != -1 matters)
    const float* __restrict__ W1,          // [3,HID]
    const float* __restrict__ b1,          // [HID]
    const float* __restrict__ w_sigma,     // [HID]
    const float* __restrict__ W_rgb,       // [HID,3]
    const float* __restrict__ W_dir,       // [3,3]
    const float* __restrict__ b_rgb,       // [3]
    float*       __restrict__ out)         // [N,OUTW]
{
    // Block-shared weight pairs: per hidden-pair jp -> {ws[j0],ws[j1],Wr0[j0],Wr0[j1]},
    //                                                  {Wr1[j0],Wr1[j1],Wr2[j0],Wr2[j1]}
    __shared__ float4 sWp[HID / 2][2];
    // Per-warp (per-ray) precomputed {S[j0],S[j1],D[j0],D[j1]} per hidden-pair
    __shared__ float4 sSD[8][HID / 2];

    const int tid  = threadIdx.x;
    const int w    = tid >> 5;
    const int lane = tid & 31;
    const int ray  = blockIdx.x * 8 + w;

    if (tid < HID / 2) {
        const int j0 = 2 * tid, j1 = j0 + 1;
        sWp[tid][0] = make_float4(w_sigma[j0], w_sigma[j1], W_rgb[j0 * 3 + 0], W_rgb[j1 * 3 + 0]);
        sWp[tid][1] = make_float4(W_rgb[j0 * 3 + 1], W_rgb[j1 * 3 + 1], W_rgb[j0 * 3 + 2], W_rgb[j1 * 3 + 2]);
    }
    __syncthreads();

    // --- per-ray scalars (broadcast loads) ---
    const float rs0 = ray_start[ray * 3 + 0];
    const float rs1 = ray_start[ray * 3 + 1];
    const float rs2 = ray_start[ray * 3 + 2];
    const float rd0 = ray_dir[ray * 3 + 0];
    const float rd1 = ray_dir[ray * 3 + 1];
    const float rd2 = ray_dir[ray * 3 + 2];

    // --- per-ray hidden precompute: S_j = start·W1[:,j]+b1[j], D_j = dir·W1[:,j] ---
    {
        const int j0 = 2 * lane, j1 = j0 + 1;
        const float w00 = W1[j0],           w01 = W1[j1];
        const float w10 = W1[HID + j0],     w11 = W1[HID + j1];
        const float w20 = W1[2 * HID + j0], w21 = W1[2 * HID + j1];
        float s0 = b1[j0] + rs0 * w00 + rs1 * w10 + rs2 * w20;
        float s1 = b1[j1] + rs0 * w01 + rs1 * w11 + rs2 * w21;
        float d0 = rd0 * w00 + rd1 * w10 + rd2 * w20;
        float d1 = rd0 * w01 + rd1 * w11 + rd2 * w21;
        sSD[w][lane] = make_float4(s0, s1, d0, d1);
    }
    __syncwarp();

    // --- load this lane's 8 contiguous samples ---
    const int base = ray * P + lane * 8;
    const float4 dA = *(const float4*)(depth + base);
    const float4 dB = *(const float4*)(depth + base + 4);
    float dep[8] = {dA.x, dA.y, dA.z, dA.w, dB.x, dB.y, dB.z, dB.w};

    unsigned long long dep2[8];
#pragma unroll
    for (int s = 0; s < 8; ++s) dep2[s] = pack2(dep[s], dep[s]);

    unsigned long long sig[8], ca[8], cb[8], cc[8];
#pragma unroll
    for (int s = 0; s < 8; ++s) { sig[s] = 0ull; ca[s] = 0ull; cb[s] = 0ull; cc[s] = 0ull; }

    // --- hidden loop over pairs of hidden units, packed f32x2 ---
#pragma unroll 4
    for (int jp = 0; jp < HID / 2; ++jp) {
        const float4 sd = sSD[w][jp];
        const float4 wa = sWp[jp][0];
        const float4 wb = sWp[jp][1];
        const unsigned long long S2  = pack2(sd.x, sd.y);
        const unsigned long long D2  = pack2(sd.z, sd.w);
        const unsigned long long ws2 = pack2(wa.x, wa.y);
        const unsigned long long wr0 = pack2(wa.z, wa.w);
        const unsigned long long wr1 = pack2(wb.x, wb.y);
        const unsigned long long wr2 = pack2(wb.z, wb.w);
#pragma unroll
        for (int s = 0; s < 8; ++s) {
            unsigned long long h = fma2(dep2[s], D2, S2);
            float hx, hy;
            unpack2(h, hx, hy);
            hx = fmaxf(hx, 0.f);
            hy = fmaxf(hy, 0.f);
            h = pack2(hx, hy);
            sig[s] = fma2(h, ws2, sig[s]);
            ca[s]  = fma2(h, wr0, ca[s]);
            cb[s]  = fma2(h, wr1, cb[s]);
            cc[s]  = fma2(h, wr2, cc[s]);
        }
    }

    // --- epilogue loads ---
    const float4 tA = *(const float4*)(dists + base);
    const float4 tB = *(const float4*)(dists + base + 4);
    const float dst[8] = {tA.x, tA.y, tA.z, tA.w, tB.x, tB.y, tB.z, tB.w};
    const int4 iA = *(const int4*)(sidx + base);
    const int4 iB = *(const int4*)(sidx + base + 4);
    const int idx[8] = {iA.x, iA.y, iA.z, iA.w, iB.x, iB.y, iB.z, iB.w};

    // --- free energy, per-lane exclusive prefix product of e = exp(-fe) ---
    float e[8], bloc[8];
    float run = 1.f;
#pragma unroll
    for (int s = 0; s < 8; ++s) {
        float sx, sy;
        unpack2(sig[s], sx, sy);
        float sigma = sx + sy;
        float fe = fmaxf(sigma, 0.f) * dst[s] * 7.0f;
        if (idx[s] == -1) fe = 0.f;
        e[s]    = __expf(-fe);
        bloc[s] = run;       // exclusive product within lane
        run *= e[s];
    }

    // --- warp-level multiplicative exclusive scan of lane totals ---
    float incl = run;
#pragma unroll
    for (int off = 1; off < 32; off <<= 1) {
        float v = __shfl_up_sync(0xffffffffu, incl, off);
        if (lane >= off) incl *= v;
    }
    float excl = __shfl_up_sync(0xffffffffu, incl, 1);
    if (lane == 0) excl = 1.f;

    // --- view-direction term for rgb ---
    const float dt0 = rd0 * W_dir[0] + rd1 * W_dir[3] + rd2 * W_dir[6] + b_rgb[0];
    const float dt1 = rd0 * W_dir[1] + rd1 * W_dir[4] + rd2 * W_dir[7] + b_rgb[1];
    const float dt2 = rd0 * W_dir[2] + rd1 * W_dir[5] + rd2 * W_dir[8] + b_rgb[2];

    float psum = 0.f, dsum = 0.f, cs0 = 0.f, cs1 = 0.f, cs2 = 0.f;
    float* orow = out + (long)ray * OUTW;

#pragma unroll
    for (int s = 0; s < 8; ++s) {
        const float bT = excl * bloc[s];          // transmittance
        const float p  = (1.f - e[s]) * bT;       // probs
        orow[5 + lane * 8 + s] = p;
        psum += p;
        dsum += dep[s] * p;
        float ax, ay, bx, by, cx, cy;
        unpack2(ca[s], ax, ay);
        unpack2(cb[s], bx, by);
        unpack2(cc[s], cx, cy);
        const float r0 = __fdividef(1.f, 1.f + __expf(-(ax + ay + dt0)));
        const float r1 = __fdividef(1.f, 1.f + __expf(-(bx + by + dt1)));
        const float r2 = __fdividef(1.f, 1.f + __expf(-(cx + cy + dt2)));
        cs0 += r0 * p;
        cs1 += r1 * p;
        cs2 += r2 * p;
    }

    // --- warp reductions ---
#pragma unroll
    for (int off = 16; off; off >>= 1) {
        psum += __shfl_xor_sync(0xffffffffu, psum, off);
        dsum += __shfl_xor_sync(0xffffffffu, dsum, off);
        cs0  += __shfl_xor_sync(0xffffffffu, cs0, off);
        cs1  += __shfl_xor_sync(0xffffffffu, cs1, off);
        cs2  += __shfl_xor_sync(0xffffffffu, cs2, off);
    }
    if (lane == 0) {
        orow[0] = cs0;
        orow[1] = cs1;
        orow[2] = cs2;
        orow[3] = dsum;
        orow[4] = 1.f - psum;
    }
}

extern "C" void kernel_launch(void* const* d_in, const int* in_sizes, int n_in,
                              void* d_out, int out_size) {
    const float* ray_start = (const float*)d_in[0];
    const float* ray_dir   = (const float*)d_in[1];
    const float* depth     = (const float*)d_in[2];
    const float* dists     = (const float*)d_in[3];
    const int*   sidx      = (const int*)d_in[4];
    const float* W1        = (const float*)d_in[5];
    const float* b1        = (const float*)d_in[6];
    const float* w_sigma   = (const float*)d_in[7];
    const float* W_rgb     = (const float*)d_in[8];
    const float* W_dir     = (const float*)d_in[9];
    const float* b_rgb     = (const float*)d_in[10];
    float* out = (float*)d_out;

    dim3 grid(N_RAYS / 8);
    dim3 block(256);
    vr_kernel<<<grid, block>>>(ray_start, ray_dir, depth, dists, sidx,
                               W1, b1, w_sigma, W_rgb, W_dir, b_rgb, out);
}

// round 3
// speedup vs baseline: 1.1431x; 1.1431x over previous
#include <cuda_runtime.h>

#define N_RAYS   8192
#define P        256
#define HID      64
#define OUTW     261   // 3 rgb + depth + missed + 256 probs
#define FULL     0xffffffffu

__device__ __forceinline__ float4 f4add(float4 a, float4 b) {
    return make_float4(a.x + b.x, a.y + b.y, a.z + b.z, a.w + b.w);
}
__device__ __forceinline__ float4 f4sub(float4 a, float4 b) {
    return make_float4(a.x - b.x, a.y - b.y, a.z - b.z, a.w - b.w);
}
__device__ __forceinline__ float4 shflup4(float4 v, int off) {
    return make_float4(__shfl_up_sync(FULL, v.x, off), __shfl_up_sync(FULL, v.y, off),
                       __shfl_up_sync(FULL, v.z, off), __shfl_up_sync(FULL, v.w, off));
}
__device__ __forceinline__ float4 shflidx4(float4 v, int src) {
    return make_float4(__shfl_sync(FULL, v.x, src), __shfl_sync(FULL, v.y, src),
                       __shfl_sync(FULL, v.z, src), __shfl_sync(FULL, v.w, src));
}

__global__ __launch_bounds__(256) void vr_kernel(
    const float* __restrict__ ray_start,   // [N,3]
    const float* __restrict__ ray_dir,     // [N,3]
    const float* __restrict__ depth,       // [N,P]
    const float* __restrict__ dists,       // [N,P]
    const int*   __restrict__ sidx,        // [N,P]
    const float* __restrict__ W1,          // [3,HID]
    const float* __restrict__ b1,          // [HID]
    const float* __restrict__ w_sigma,     // [HID]
    const float* __restrict__ W_rgb,       // [HID,3]
    const float* __restrict__ W_dir,       // [3,3]
    const float* __restrict__ b_rgb,       // [3]
    float*       __restrict__ out)         // [N,OUTW]
{
    // per-warp: sorted crossing depths + prefix-sum tables (65 entries, [64]=total)
    __shared__ float  s_ts [8][64];
    __shared__ float4 s_PPS[8][65];   // prefix of POS-group S-payload (sig,r0,r1,r2)
    __shared__ float4 s_PPD[8][65];   // prefix of POS-group D-payload
    __shared__ float4 s_PNS[8][65];   // prefix of NEG-group S-payload
    __shared__ float4 s_PND[8][65];   // prefix of NEG-group D-payload

    const int tid  = threadIdx.x;
    const int w    = tid >> 5;
    const int lane = tid & 31;
    const int ray  = blockIdx.x * 8 + w;

    // --- per-ray scalars ---
    const float rs0 = ray_start[ray * 3 + 0];
    const float rs1 = ray_start[ray * 3 + 1];
    const float rs2 = ray_start[ray * 3 + 2];
    const float rd0 = ray_dir[ray * 3 + 0];
    const float rd1 = ray_dir[ray * 3 + 1];
    const float rd2 = ray_dir[ray * 3 + 2];

    // --- per-unit setup: lane owns units uA=lane, uB=lane+32 ---
    float kA, kB;          // crossing depths (keys)
    int   posA, posB;      // group flags
    float4 paySA, payDA, paySB, payDB;

#pragma unroll
    for (int half = 0; half < 2; ++half) {
        const int u = lane + half * 32;
        const float w1x = W1[u], w1y = W1[HID + u], w1z = W1[2 * HID + u];
        const float S = b1[u] + rs0 * w1x + rs1 * w1y + rs2 * w1z;
        const float D = rd0 * w1x + rd1 * w1y + rd2 * w1z;
        const float ws  = w_sigma[u];
        const float wr0 = W_rgb[u * 3 + 0];
        const float wr1 = W_rgb[u * 3 + 1];
        const float wr2 = W_rgb[u * 3 + 2];
        float t;
        int isPos;
        if (D > 0.f)      { t = __fdividef(-S, D); isPos = 1; }
        else if (D < 0.f) { t = __fdividef(-S, D); isPos = 0; }
        else              { t = (S > 0.f) ? -1e30f : 1e30f; isPos = 1; }
        float4 pS = make_float4(ws * S, wr0 * S, wr1 * S, wr2 * S);
        float4 pD = make_float4(ws * D, wr0 * D, wr1 * D, wr2 * D);
        if (half == 0) { kA = t; posA = isPos; paySA = pS; payDA = pD; }
        else           { kB = t; posB = isPos; paySB = pS; payDB = pD; }
    }

    // --- counting-rank via shuffles (ids: uA=lane, uB=lane+32; ties by id) ---
    int rA = 0, rB = 0;
#pragma unroll
    for (int src = 0; src < 32; ++src) {
        const float oA = __shfl_sync(FULL, kA, src);   // unit src
        const float oB = __shfl_sync(FULL, kB, src);   // unit src+32
        rA += (oA < kA) | ((oA == kA) & (src < lane));
        rA += (oB < kA);                                // src+32 > lane always
        rB += (oA < kB) | (oA == kB);                   // src < lane+32 always
        rB += (oB < kB) | ((oB == kB) & (src < lane));
    }

    // --- scatter masked payloads into sorted-position slots ---
    const float4 z4 = make_float4(0.f, 0.f, 0.f, 0.f);
    s_ts[w][rA]  = kA;
    s_PPS[w][rA] = posA ? paySA : z4;
    s_PPD[w][rA] = posA ? payDA : z4;
    s_PNS[w][rA] = posA ? z4 : paySA;
    s_PND[w][rA] = posA ? z4 : payDA;
    s_ts[w][rB]  = kB;
    s_PPS[w][rB] = posB ? paySB : z4;
    s_PPD[w][rB] = posB ? payDB : z4;
    s_PNS[w][rB] = posB ? z4 : paySB;
    s_PND[w][rB] = posB ? z4 : payDB;
    __syncwarp();

    // --- in-place 16-channel exclusive scan over 64 sorted positions ---
    const int p0 = 2 * lane, p1 = p0 + 1;
    const float4 aS0 = s_PPS[w][p0], aS1 = s_PPS[w][p1];
    const float4 aD0 = s_PPD[w][p0], aD1 = s_PPD[w][p1];
    const float4 bS0 = s_PNS[w][p0], bS1 = s_PNS[w][p1];
    const float4 bD0 = s_PND[w][p0], bD1 = s_PND[w][p1];

    float4 iPS = f4add(aS0, aS1);
    float4 iPD = f4add(aD0, aD1);
    float4 iNS = f4add(bS0, bS1);
    float4 iND = f4add(bD0, bD1);
#pragma unroll
    for (int off = 1; off < 32; off <<= 1) {
        float4 tPS = shflup4(iPS, off);
        float4 tPD = shflup4(iPD, off);
        float4 tNS = shflup4(iNS, off);
        float4 tND = shflup4(iND, off);
        if (lane >= off) {
            iPS = f4add(iPS, tPS);
            iPD = f4add(iPD, tPD);
            iNS = f4add(iNS, tNS);
            iND = f4add(iND, tND);
        }
    }
    float4 ePS = shflup4(iPS, 1);
    float4 ePD = shflup4(iPD, 1);
    float4 eNS = shflup4(iNS, 1);
    float4 eND = shflup4(iND, 1);
    if (lane == 0) { ePS = z4; ePD = z4; eNS = z4; eND = z4; }
    const float4 totNS = shflidx4(iNS, 31);
    const float4 totND = shflidx4(iND, 31);
    __syncwarp();   // all reads of scattered slots done before overwrite
    s_PPS[w][p0] = ePS; s_PPS[w][p1] = f4add(ePS, aS0);
    s_PPD[w][p0] = ePD; s_PPD[w][p1] = f4add(ePD, aD0);
    s_PNS[w][p0] = eNS; s_PNS[w][p1] = f4add(eNS, bS0);
    s_PND[w][p0] = eND; s_PND[w][p1] = f4add(eND, bD0);
    if (lane == 31) {
        s_PPS[w][64] = iPS; s_PPD[w][64] = iPD;
        s_PNS[w][64] = iNS; s_PND[w][64] = iND;
    }
    __syncwarp();

    // --- load this lane's 8 contiguous samples ---
    const int base = ray * P + lane * 8;
    const float4 dA4 = *(const float4*)(depth + base);
    const float4 dB4 = *(const float4*)(depth + base + 4);
    const float dep[8] = {dA4.x, dA4.y, dA4.z, dA4.w, dB4.x, dB4.y, dB4.z, dB4.w};
    const float4 tA4 = *(const float4*)(dists + base);
    const float4 tB4 = *(const float4*)(dists + base + 4);
    const float dst[8] = {tA4.x, tA4.y, tA4.z, tA4.w, tB4.x, tB4.y, tB4.z, tB4.w};
    const int4 iA4 = *(const int4*)(sidx + base);
    const int4 iB4 = *(const int4*)(sidx + base + 4);
    const int idx[8] = {iA4.x, iA4.y, iA4.z, iA4.w, iB4.x, iB4.y, iB4.z, iB4.w};

    const float* ts = s_ts[w];

    // --- per-sample: rank lookup -> 4 outputs; then free energy ---
    float e[8], bloc[8], l0a[8], l1a[8], l2a[8];
    float run = 1.f;
#pragma unroll
    for (int s = 0; s < 8; ++s) {
        const float d = dep[s];
        int c;
        if (ts[63] <= d) c = 64;
        else {
            c = 0;
            if (ts[c + 31] <= d) c += 32;
            if (ts[c + 15] <= d) c += 16;
            if (ts[c + 7]  <= d) c += 8;
            if (ts[c + 3]  <= d) c += 4;
            if (ts[c + 1]  <= d) c += 2;
            if (ts[c]      <= d) c += 1;
        }
        const float4 PS = s_PPS[w][c];
        const float4 PD = s_PPD[w][c];
        const float4 NS = f4sub(totNS, s_PNS[w][c]);
        const float4 ND = f4sub(totND, s_PND[w][c]);
        const float4 A  = f4add(PS, NS);
        const float4 B  = f4add(PD, ND);
        const float sigma = A.x + d * B.x;
        l0a[s] = A.y + d * B.y;
        l1a[s] = A.z + d * B.z;
        l2a[s] = A.w + d * B.w;

        float fe = fmaxf(sigma, 0.f) * dst[s] * 7.0f;
        if (idx[s] == -1) fe = 0.f;
        e[s]    = __expf(-fe);
        bloc[s] = run;
        run *= e[s];
    }

    // --- warp multiplicative exclusive scan of lane products ---
    float incl = run;
#pragma unroll
    for (int off = 1; off < 32; off <<= 1) {
        float v = __shfl_up_sync(FULL, incl, off);
        if (lane >= off) incl *= v;
    }
    float excl = __shfl_up_sync(FULL, incl, 1);
    if (lane == 0) excl = 1.f;

    // --- view-direction rgb bias ---
    const float dt0 = rd0 * W_dir[0] + rd1 * W_dir[3] + rd2 * W_dir[6] + b_rgb[0];
    const float dt1 = rd0 * W_dir[1] + rd1 * W_dir[4] + rd2 * W_dir[7] + b_rgb[1];
    const float dt2 = rd0 * W_dir[2] + rd1 * W_dir[5] + rd2 * W_dir[8] + b_rgb[2];

    float psum = 0.f, dsum = 0.f, cs0 = 0.f, cs1 = 0.f, cs2 = 0.f;
    float* orow = out + (long)ray * OUTW;

#pragma unroll
    for (int s = 0; s < 8; ++s) {
        const float bT = excl * bloc[s];
        const float p  = (1.f - e[s]) * bT;
        orow[5 + lane * 8 + s] = p;
        psum += p;
        dsum += dep[s] * p;
        const float r0 = __fdividef(1.f, 1.f + __expf(-(l0a[s] + dt0)));
        const float r1 = __fdividef(1.f, 1.f + __expf(-(l1a[s] + dt1)));
        const float r2 = __fdividef(1.f, 1.f + __expf(-(l2a[s] + dt2)));
        cs0 += r0 * p;
        cs1 += r1 * p;
        cs2 += r2 * p;
    }

#pragma unroll
    for (int off = 16; off; off >>= 1) {
        psum += __shfl_xor_sync(FULL, psum, off);
        dsum += __shfl_xor_sync(FULL, dsum, off);
        cs0  += __shfl_xor_sync(FULL, cs0, off);
        cs1  += __shfl_xor_sync(FULL, cs1, off);
        cs2  += __shfl_xor_sync(FULL, cs2, off);
    }
    if (lane == 0) {
        orow[0] = cs0;
        orow[1] = cs1;
        orow[2] = cs2;
        orow[3] = dsum;
        orow[4] = 1.f - psum;
    }
}

extern "C" void kernel_launch(void* const* d_in, const int* in_sizes, int n_in,
                              void* d_out, int out_size) {
    const float* ray_start = (const float*)d_in[0];
    const float* ray_dir   = (const float*)d_in[1];
    const float* depth     = (const float*)d_in[2];
    const float* dists     = (const float*)d_in[3];
    const int*   sidx      = (const int*)d_in[4];
    const float* W1        = (const float*)d_in[5];
    const float* b1        = (const float*)d_in[6];
    const float* w_sigma   = (const float*)d_in[7];
    const float* W_rgb     = (const float*)d_in[8];
    const float* W_dir     = (const float*)d_in[9];
    const float* b_rgb     = (const float*)d_in[10];
    float* out = (float*)d_out;

    vr_kernel<<<N_RAYS / 8, 256>>>(ray_start, ray_dir, depth, dists, sidx,
                                   W1, b1, w_sigma, W_rgb, W_dir, b_rgb, out);
}

// round 6
// speedup vs baseline: 1.6896x; 1.4780x over previous
#include <cuda_runtime.h>

#define N_RAYS   8192
#define P        256
#define HID      64
#define OUTW     261   // 3 rgb + depth + missed + 256 probs
#define FULL     0xffffffffu

__device__ __forceinline__ float4 f4add(float4 a, float4 b) {
    return make_float4(a.x + b.x, a.y + b.y, a.z + b.z, a.w + b.w);
}
__device__ __forceinline__ float4 shflup4(float4 v, int off) {
    return make_float4(__shfl_up_sync(FULL, v.x, off), __shfl_up_sync(FULL, v.y, off),
                       __shfl_up_sync(FULL, v.z, off), __shfl_up_sync(FULL, v.w, off));
}

__global__ __launch_bounds__(256) void vr_kernel(
    const float* __restrict__ ray_start,   // [N,3]
    const float* __restrict__ ray_dir,     // [N,3]
    const float* __restrict__ depth,       // [N,P]
    const float* __restrict__ dists,       // [N,P]
    const int*   __restrict__ sidx,        // [N,P]
    const float* __restrict__ W1,          // [3,HID]
    const float* __restrict__ b1,          // [HID]
    const float* __restrict__ w_sigma,     // [HID]
    const float* __restrict__ W_rgb,       // [HID,3]
    const float* __restrict__ W_dir,       // [3,3]
    const float* __restrict__ b_rgb,       // [3]
    float*       __restrict__ out)         // [N,OUTW]
{
    // per-warp: sorted crossing depths + combined prefix tables
    //   s_TS[c] = totN_S + sum_{p<c} sigma_p * payS_p   (sig,r0,r1,r2)
    //   s_TD[c] = totN_D + sum_{p<c} sigma_p * payD_p
    __shared__ float  s_ts[8][64];
    __shared__ float4 s_TS[8][65];
    __shared__ float4 s_TD[8][65];

    const int tid  = threadIdx.x;
    const int w    = tid >> 5;
    const int lane = tid & 31;
    const int ray  = blockIdx.x * 8 + w;

    // --- per-ray scalars ---
    const float rs0 = ray_start[ray * 3 + 0];
    const float rs1 = ray_start[ray * 3 + 1];
    const float rs2 = ray_start[ray * 3 + 2];
    const float rd0 = ray_dir[ray * 3 + 0];
    const float rd1 = ray_dir[ray * 3 + 1];
    const float rd2 = ray_dir[ray * 3 + 2];

    // --- per-unit setup: lane owns units uA=lane, uB=lane+32 ---
    float kA, kB;
    float4 sgSA, sgDA, sgSB, sgDB;     // signed payloads
    float4 negS = make_float4(0.f, 0.f, 0.f, 0.f);
    float4 negD = make_float4(0.f, 0.f, 0.f, 0.f);

#pragma unroll
    for (int half = 0; half < 2; ++half) {
        const int u = lane + half * 32;
        const float w1x = W1[u], w1y = W1[HID + u], w1z = W1[2 * HID + u];
        const float S = b1[u] + rs0 * w1x + rs1 * w1y + rs2 * w1z;
        const float D = rd0 * w1x + rd1 * w1y + rd2 * w1z;
        const float ws  = w_sigma[u];
        const float wr0 = W_rgb[u * 3 + 0];
        const float wr1 = W_rgb[u * 3 + 1];
        const float wr2 = W_rgb[u * 3 + 2];
        float t;
        int isPos;
        if (D > 0.f)      { t = __fdividef(-S, D); isPos = 1; }
        else if (D < 0.f) { t = __fdividef(-S, D); isPos = 0; }
        else              { t = (S > 0.f) ? -1e30f : 1e30f; isPos = 1; }
        const float sgn = isPos ? 1.f : -1.f;
        float4 pS = make_float4(ws * S, wr0 * S, wr1 * S, wr2 * S);
        float4 pD = make_float4(ws * D, wr0 * D, wr1 * D, wr2 * D);
        if (!isPos) {
            negS = f4add(negS, pS);
            negD = f4add(negD, pD);
        }
        float4 gS = make_float4(sgn * pS.x, sgn * pS.y, sgn * pS.z, sgn * pS.w);
        float4 gD = make_float4(sgn * pD.x, sgn * pD.y, sgn * pD.z, sgn * pD.w);
        if (half == 0) { kA = t; sgSA = gS; sgDA = gD; }
        else           { kB = t; sgSB = gS; sgDB = gD; }
    }

    // --- warp reduction: totals of neg-group payloads (8 channels) ---
#pragma unroll
    for (int off = 16; off; off >>= 1) {
        negS.x += __shfl_xor_sync(FULL, negS.x, off);
        negS.y += __shfl_xor_sync(FULL, negS.y, off);
        negS.z += __shfl_xor_sync(FULL, negS.z, off);
        negS.w += __shfl_xor_sync(FULL, negS.w, off);
        negD.x += __shfl_xor_sync(FULL, negD.x, off);
        negD.y += __shfl_xor_sync(FULL, negD.y, off);
        negD.z += __shfl_xor_sync(FULL, negD.z, off);
        negD.w += __shfl_xor_sync(FULL, negD.w, off);
    }

    // --- counting-rank via shuffles (ids: uA=lane, uB=lane+32; ties by id) ---
    int rA = 0, rB = 0;
#pragma unroll
    for (int src = 0; src < 32; ++src) {
        const float oA = __shfl_sync(FULL, kA, src);
        const float oB = __shfl_sync(FULL, kB, src);
        rA += (oA < kA) | ((oA == kA) & (src < lane));
        rA += (oB < kA);
        rB += (oA < kB) | (oA == kB);
        rB += (oB < kB) | ((oB == kB) & (src < lane));
    }

    // --- scatter signed payloads into sorted-position slots ---
    s_ts[w][rA] = kA;
    s_TS[w][rA] = sgSA;
    s_TD[w][rA] = sgDA;
    s_ts[w][rB] = kB;
    s_TS[w][rB] = sgSB;
    s_TD[w][rB] = sgDB;
    __syncwarp();

    // --- 8-channel exclusive scan over 64 sorted positions, bake in totN ---
    const int p0 = 2 * lane, p1 = p0 + 1;
    const float4 aS0 = s_TS[w][p0], aS1 = s_TS[w][p1];
    const float4 aD0 = s_TD[w][p0], aD1 = s_TD[w][p1];

    float4 iS = f4add(aS0, aS1);
    float4 iD = f4add(aD0, aD1);
#pragma unroll
    for (int off = 1; off < 32; off <<= 1) {
        float4 tS = shflup4(iS, off);
        float4 tD = shflup4(iD, off);
        if (lane >= off) {
            iS = f4add(iS, tS);
            iD = f4add(iD, tD);
        }
    }
    float4 eS = shflup4(iS, 1);
    float4 eD = shflup4(iD, 1);
    if (lane == 0) {
        eS = make_float4(0.f, 0.f, 0.f, 0.f);
        eD = make_float4(0.f, 0.f, 0.f, 0.f);
    }
    __syncwarp();   // reads of scattered slots complete before overwrite
    const float4 b0S = f4add(negS, eS);
    const float4 b0D = f4add(negD, eD);
    s_TS[w][p0] = b0S;  s_TS[w][p1] = f4add(b0S, aS0);
    s_TD[w][p0] = b0D;  s_TD[w][p1] = f4add(b0D, aD0);
    if (lane == 31) {
        s_TS[w][64] = f4add(negS, iS);
        s_TD[w][64] = f4add(negD, iD);
    }
    __syncwarp();

    // --- load this lane's 8 contiguous samples ---
    const int base = ray * P + lane * 8;
    const float4 dA4 = *(const float4*)(depth + base);
    const float4 dB4 = *(const float4*)(depth + base + 4);
    const float dep[8] = {dA4.x, dA4.y, dA4.z, dA4.w, dB4.x, dB4.y, dB4.z, dB4.w};
    const float4 tA4 = *(const float4*)(dists + base);
    const float4 tB4 = *(const float4*)(dists + base + 4);
    const float dst[8] = {tA4.x, tA4.y, tA4.z, tA4.w, tB4.x, tB4.y, tB4.z, tB4.w};
    const int4 iA4 = *(const int4*)(sidx + base);
    const int4 iB4 = *(const int4*)(sidx + base + 4);
    const int idx[8] = {iA4.x, iA4.y, iA4.z, iA4.w, iB4.x, iB4.y, iB4.z, iB4.w};

    const float* ts = s_ts[w];

    // --- rank for first sample: binary search (c = #{t_p <= d}) ---
    int c;
    {
        const float d = dep[0];
        if (ts[63] <= d) c = 64;
        else {
            c = 0;
            if (ts[c + 31] <= d) c += 32;
            if (ts[c + 15] <= d) c += 16;
            if (ts[c + 7]  <= d) c += 8;
            if (ts[c + 3]  <= d) c += 4;
            if (ts[c + 1]  <= d) c += 2;
            if (ts[c]      <= d) c += 1;
        }
    }
    float4 TS = s_TS[w][c];
    float4 TD = s_TD[w][c];

    // --- per-sample evaluation + free energy ---
    float e[8], bloc[8], l0a[8], l1a[8], l2a[8];
    float run = 1.f;
#pragma unroll
    for (int s = 0; s < 8; ++s) {
        const float d = dep[s];
        if (s > 0) {
            bool moved = false;
            while (c < 64 && ts[c] <= d) { ++c; moved = true; }
            if (moved) { TS = s_TS[w][c]; TD = s_TD[w][c]; }
        }
        const float sigma = TS.x + d * TD.x;
        l0a[s] = TS.y + d * TD.y;
        l1a[s] = TS.z + d * TD.z;
        l2a[s] = TS.w + d * TD.w;

        float fe = fmaxf(sigma, 0.f) * dst[s] * 7.0f;
        if (idx[s] == -1) fe = 0.f;
        e[s]    = __expf(-fe);
        bloc[s] = run;
        run *= e[s];
    }

    // --- warp multiplicative exclusive scan of lane products ---
    float incl = run;
#pragma unroll
    for (int off = 1; off < 32; off <<= 1) {
        float v = __shfl_up_sync(FULL, incl, off);
        if (lane >= off) incl *= v;
    }
    float excl = __shfl_up_sync(FULL, incl, 1);
    if (lane == 0) excl = 1.f;

    // --- view-direction rgb bias ---
    const float dt0 = rd0 * W_dir[0] + rd1 * W_dir[3] + rd2 * W_dir[6] + b_rgb[0];
    const float dt1 = rd0 * W_dir[1] + rd1 * W_dir[4] + rd2 * W_dir[7] + b_rgb[1];
    const float dt2 = rd0 * W_dir[2] + rd1 * W_dir[5] + rd2 * W_dir[8] + b_rgb[2];

    float psum = 0.f, dsum = 0.f, cs0 = 0.f, cs1 = 0.f, cs2 = 0.f;
    float* orow = out + (long)ray * OUTW;

#pragma unroll
    for (int s = 0; s < 8; ++s) {
        const float bT = excl * bloc[s];
        const float p  = (1.f - e[s]) * bT;
        orow[5 + lane * 8 + s] = p;
        psum += p;
        dsum += dep[s] * p;
        const float r0 = __fdividef(1.f, 1.f + __expf(-(l0a[s] + dt0)));
        const float r1 = __fdividef(1.f, 1.f + __expf(-(l1a[s] + dt1)));
        const float r2 = __fdividef(1.f, 1.f + __expf(-(l2a[s] + dt2)));
        cs0 += r0 * p;
        cs1 += r1 * p;
        cs2 += r2 * p;
    }

#pragma unroll
    for (int off = 16; off; off >>= 1) {
        psum += __shfl_xor_sync(FULL, psum, off);
        dsum += __shfl_xor_sync(FULL, dsum, off);
        cs0  += __shfl_xor_sync(FULL, cs0, off);
        cs1  += __shfl_xor_sync(FULL, cs1, off);
        cs2  += __shfl_xor_sync(FULL, cs2, off);
    }
    if (lane == 0) {
        orow[0] = cs0;
        orow[1] = cs1;
        orow[2] = cs2;
        orow[3] = dsum;
        orow[4] = 1.f - psum;
    }
}

extern "C" void kernel_launch(void* const* d_in, const int* in_sizes, int n_in,
                              void* d_out, int out_size) {
    const float* ray_start = (const float*)d_in[0];
    const float* ray_dir   = (const float*)d_in[1];
    const float* depth     = (const float*)d_in[2];
    const float* dists     = (const float*)d_in[3];
    const int*   sidx      = (const int*)d_in[4];
    const float* W1        = (const float*)d_in[5];
    const float* b1        = (const float*)d_in[6];
    const float* w_sigma   = (const float*)d_in[7];
    const float* W_rgb     = (const float*)d_in[8];
    const float* W_dir     = (const float*)d_in[9];
    const float* b_rgb     = (const float*)d_in[10];
    float* out = (float*)d_out;

    vr_kernel<<<N_RAYS / 8, 256>>>(ray_start, ray_dir, depth, dists, sidx,
                                   W1, b1, w_sigma, W_rgb, W_dir, b_rgb, out);
}

// round 7
// speedup vs baseline: 1.7107x; 1.0125x over previous
#include <cuda_runtime.h>

#define N_RAYS   8192
#define P        256
#define HID      64
#define OUTW     261   // 3 rgb + depth + missed + 256 probs
#define FULL     0xffffffffu

__device__ __forceinline__ float4 f4add(float4 a, float4 b) {
    return make_float4(a.x + b.x, a.y + b.y, a.z + b.z, a.w + b.w);
}
__device__ __forceinline__ float4 shflup4(float4 v, int off) {
    return make_float4(__shfl_up_sync(FULL, v.x, off), __shfl_up_sync(FULL, v.y, off),
                       __shfl_up_sync(FULL, v.z, off), __shfl_up_sync(FULL, v.w, off));
}

__global__ __launch_bounds__(256) void vr_kernel(
    const float* __restrict__ ray_start,   // [N,3]
    const float* __restrict__ ray_dir,     // [N,3]
    const float* __restrict__ depth,       // [N,P]
    const float* __restrict__ dists,       // [N,P]
    const int*   __restrict__ sidx,        // [N,P]
    const float* __restrict__ W1,          // [3,HID]
    const float* __restrict__ b1,          // [HID]
    const float* __restrict__ w_sigma,     // [HID]
    const float* __restrict__ W_rgb,       // [HID,3]
    const float* __restrict__ W_dir,       // [3,3]
    const float* __restrict__ b_rgb,       // [3]
    float*       __restrict__ out)         // [N,OUTW]
{
    __shared__ float  s_ts[8][64];
    __shared__ float4 s_TS[8][65];    // totN_S + signed prefix of S-payload (sig,r0,r1,r2)
    __shared__ float4 s_TD[8][65];    // totN_D + signed prefix of D-payload
    __shared__ float  s_pb[8][288];   // probs staging, stride-9 per owner lane (CF banks)

    const int tid  = threadIdx.x;
    const int w    = tid >> 5;
    const int lane = tid & 31;
    const int ray  = blockIdx.x * 8 + w;

    // --- per-ray scalars ---
    const float rs0 = ray_start[ray * 3 + 0];
    const float rs1 = ray_start[ray * 3 + 1];
    const float rs2 = ray_start[ray * 3 + 2];
    const float rd0 = ray_dir[ray * 3 + 0];
    const float rd1 = ray_dir[ray * 3 + 1];
    const float rd2 = ray_dir[ray * 3 + 2];

    // --- per-unit setup: lane owns units uA=lane, uB=lane+32 ---
    float kA, kB;
    float4 sgSA, sgDA, sgSB, sgDB;
    float4 negS = make_float4(0.f, 0.f, 0.f, 0.f);
    float4 negD = make_float4(0.f, 0.f, 0.f, 0.f);

#pragma unroll
    for (int half = 0; half < 2; ++half) {
        const int u = lane + half * 32;
        const float w1x = W1[u], w1y = W1[HID + u], w1z = W1[2 * HID + u];
        const float S = b1[u] + rs0 * w1x + rs1 * w1y + rs2 * w1z;
        const float D = rd0 * w1x + rd1 * w1y + rd2 * w1z;
        const float ws  = w_sigma[u];
        const float wr0 = W_rgb[u * 3 + 0];
        const float wr1 = W_rgb[u * 3 + 1];
        const float wr2 = W_rgb[u * 3 + 2];
        float t;
        int isPos;
        if (D > 0.f)      { t = __fdividef(-S, D); isPos = 1; }
        else if (D < 0.f) { t = __fdividef(-S, D); isPos = 0; }
        else              { t = (S > 0.f) ? -1e30f : 1e30f; isPos = 1; }
        const float sgn = isPos ? 1.f : -1.f;
        float4 pS = make_float4(ws * S, wr0 * S, wr1 * S, wr2 * S);
        float4 pD = make_float4(ws * D, wr0 * D, wr1 * D, wr2 * D);
        if (!isPos) {
            negS = f4add(negS, pS);
            negD = f4add(negD, pD);
        }
        float4 gS = make_float4(sgn * pS.x, sgn * pS.y, sgn * pS.z, sgn * pS.w);
        float4 gD = make_float4(sgn * pD.x, sgn * pD.y, sgn * pD.z, sgn * pD.w);
        if (half == 0) { kA = t; sgSA = gS; sgDA = gD; }
        else           { kB = t; sgSB = gS; sgDB = gD; }
    }

    // --- warp reduction: neg-group totals (8 channels) ---
#pragma unroll
    for (int off = 16; off; off >>= 1) {
        negS.x += __shfl_xor_sync(FULL, negS.x, off);
        negS.y += __shfl_xor_sync(FULL, negS.y, off);
        negS.z += __shfl_xor_sync(FULL, negS.z, off);
        negS.w += __shfl_xor_sync(FULL, negS.w, off);
        negD.x += __shfl_xor_sync(FULL, negD.x, off);
        negD.y += __shfl_xor_sync(FULL, negD.y, off);
        negD.z += __shfl_xor_sync(FULL, negD.z, off);
        negD.w += __shfl_xor_sync(FULL, negD.w, off);
    }

    // --- counting rank (ties by id) ---
    int rA = 0, rB = 0;
#pragma unroll
    for (int src = 0; src < 32; ++src) {
        const float oA = __shfl_sync(FULL, kA, src);
        const float oB = __shfl_sync(FULL, kB, src);
        rA += (oA < kA) | ((oA == kA) & (src < lane));
        rA += (oB < kA);
        rB += (oA < kB) | (oA == kB);
        rB += (oB < kB) | ((oB == kB) & (src < lane));
    }

    // --- scatter signed payloads into sorted slots ---
    s_ts[w][rA] = kA;
    s_TS[w][rA] = sgSA;
    s_TD[w][rA] = sgDA;
    s_ts[w][rB] = kB;
    s_TS[w][rB] = sgSB;
    s_TD[w][rB] = sgDB;
    __syncwarp();

    // --- 8-channel exclusive scan over 64 slots, bake totN into base ---
    const int p0 = 2 * lane, p1 = p0 + 1;
    const float4 aS0 = s_TS[w][p0], aS1 = s_TS[w][p1];
    const float4 aD0 = s_TD[w][p0], aD1 = s_TD[w][p1];

    float4 iS = f4add(aS0, aS1);
    float4 iD = f4add(aD0, aD1);
#pragma unroll
    for (int off = 1; off < 32; off <<= 1) {
        float4 tS = shflup4(iS, off);
        float4 tD = shflup4(iD, off);
        if (lane >= off) {
            iS = f4add(iS, tS);
            iD = f4add(iD, tD);
        }
    }
    float4 eS = shflup4(iS, 1);
    float4 eD = shflup4(iD, 1);
    if (lane == 0) {
        eS = make_float4(0.f, 0.f, 0.f, 0.f);
        eD = make_float4(0.f, 0.f, 0.f, 0.f);
    }
    __syncwarp();
    const float4 b0S = f4add(negS, eS);
    const float4 b0D = f4add(negD, eD);
    s_TS[w][p0] = b0S;  s_TS[w][p1] = f4add(b0S, aS0);
    s_TD[w][p0] = b0D;  s_TD[w][p1] = f4add(b0D, aD0);
    if (lane == 31) {
        s_TS[w][64] = f4add(negS, iS);
        s_TD[w][64] = f4add(negD, iD);
    }
    __syncwarp();

    // --- load this lane's 8 contiguous samples ---
    const int base = ray * P + lane * 8;
    const float4 dA4 = *(const float4*)(depth + base);
    const float4 dB4 = *(const float4*)(depth + base + 4);
    const float dep[8] = {dA4.x, dA4.y, dA4.z, dA4.w, dB4.x, dB4.y, dB4.z, dB4.w};
    const float4 tA4 = *(const float4*)(dists + base);
    const float4 tB4 = *(const float4*)(dists + base + 4);
    const float dst[8] = {tA4.x, tA4.y, tA4.z, tA4.w, tB4.x, tB4.y, tB4.z, tB4.w};
    const int4 iA4 = *(const int4*)(sidx + base);
    const int4 iB4 = *(const int4*)(sidx + base + 4);
    const int idx[8] = {iA4.x, iA4.y, iA4.z, iA4.w, iB4.x, iB4.y, iB4.z, iB4.w};

    const float* ts = s_ts[w];

    // --- view-direction rgb bias (needed inside fused loop) ---
    const float dt0 = rd0 * W_dir[0] + rd1 * W_dir[3] + rd2 * W_dir[6] + b_rgb[0];
    const float dt1 = rd0 * W_dir[1] + rd1 * W_dir[4] + rd2 * W_dir[7] + b_rgb[1];
    const float dt2 = rd0 * W_dir[2] + rd1 * W_dir[5] + rd2 * W_dir[8] + b_rgb[2];

    // --- rank for first sample ---
    int c;
    {
        const float d = dep[0];
        if (ts[63] <= d) c = 64;
        else {
            c = 0;
            if (ts[c + 31] <= d) c += 32;
            if (ts[c + 15] <= d) c += 16;
            if (ts[c + 7]  <= d) c += 8;
            if (ts[c + 3]  <= d) c += 4;
            if (ts[c + 1]  <= d) c += 2;
            if (ts[c]      <= d) c += 1;
        }
    }
    float4 TS = s_TS[w][c];
    float4 TD = s_TD[w][c];

    // --- fused per-sample loop: eval + free energy + pre-scaled epilogue sums ---
    // p[s] = excl * q[s] with q = (1-e)*run_prev; excl multiplied in after scan.
    float q[8];
    float qs = 0.f, qd = 0.f, qc0 = 0.f, qc1 = 0.f, qc2 = 0.f;
    float run = 1.f;
#pragma unroll
    for (int s = 0; s < 8; ++s) {
        const float d = dep[s];
        if (s > 0) {
            bool moved = false;
            while (c < 64 && ts[c] <= d) { ++c; moved = true; }
            if (moved) { TS = s_TS[w][c]; TD = s_TD[w][c]; }
        }
        const float sigma = TS.x + d * TD.x;
        const float l0 = TS.y + d * TD.y;
        const float l1 = TS.z + d * TD.z;
        const float l2 = TS.w + d * TD.w;

        float fe = fmaxf(sigma, 0.f) * dst[s] * 7.0f;
        if (idx[s] == -1) fe = 0.f;
        const float es = __expf(-fe);
        const float qq = (1.f - es) * run;
        run *= es;
        q[s] = qq;

        qs += qq;
        qd += d * qq;
        const float r0 = __fdividef(1.f, 1.f + __expf(-(l0 + dt0)));
        const float r1 = __fdividef(1.f, 1.f + __expf(-(l1 + dt1)));
        const float r2 = __fdividef(1.f, 1.f + __expf(-(l2 + dt2)));
        qc0 += r0 * qq;
        qc1 += r1 * qq;
        qc2 += r2 * qq;
    }

    // --- warp multiplicative exclusive scan of lane products ---
    float incl = run;
#pragma unroll
    for (int off = 1; off < 32; off <<= 1) {
        float v = __shfl_up_sync(FULL, incl, off);
        if (lane >= off) incl *= v;
    }
    float excl = __shfl_up_sync(FULL, incl, 1);
    if (lane == 0) excl = 1.f;

    // --- finalize lane partials ---
    float psum = excl * qs;
    float dsum = excl * qd;
    float cs0  = excl * qc0;
    float cs1  = excl * qc1;
    float cs2  = excl * qc2;

    // --- stage probs in shared (stride-9, conflict-free), emit coalesced stores ---
    {
        float* pb = s_pb[w];
        const int sb = lane * 9;
#pragma unroll
        for (int s = 0; s < 8; ++s) pb[sb + s] = excl * q[s];
        __syncwarp();
        float* orow = out + (long)ray * OUTW;
#pragma unroll
        for (int i = 0; i < 8; ++i) {
            const int m = i * 32 + lane;              // output sample index
            orow[5 + m] = pb[(m >> 3) * 9 + (m & 7)];
        }

        // --- warp reductions for the 5 header values ---
#pragma unroll
        for (int off = 16; off; off >>= 1) {
            psum += __shfl_xor_sync(FULL, psum, off);
            dsum += __shfl_xor_sync(FULL, dsum, off);
            cs0  += __shfl_xor_sync(FULL, cs0, off);
            cs1  += __shfl_xor_sync(FULL, cs1, off);
            cs2  += __shfl_xor_sync(FULL, cs2, off);
        }
        if (lane == 0) {
            orow[0] = cs0;
            orow[1] = cs1;
            orow[2] = cs2;
            orow[3] = dsum;
            orow[4] = 1.f - psum;
        }
    }
}

extern "C" void kernel_launch(void* const* d_in, const int* in_sizes, int n_in,
                              void* d_out, int out_size) {
    const float* ray_start = (const float*)d_in[0];
    const float* ray_dir   = (const float*)d_in[1];
    const float* depth     = (const float*)d_in[2];
    const float* dists     = (const float*)d_in[3];
    const int*   sidx      = (const int*)d_in[4];
    const float* W1        = (const float*)d_in[5];
    const float* b1        = (const float*)d_in[6];
    const float* w_sigma   = (const float*)d_in[7];
    const float* W_rgb     = (const float*)d_in[8];
    const float* W_dir     = (const float*)d_in[9];
    const float* b_rgb     = (const float*)d_in[10];
    float* out = (float*)d_out;

    vr_kernel<<<N_RAYS / 8, 256>>>(ray_start, ray_dir, depth, dists, sidx,
                                   W1, b1, w_sigma, W_rgb, W_dir, b_rgb, out);
}

// round 8
// speedup vs baseline: 1.8524x; 1.0828x over previous
#include <cuda_runtime.h>

#define N_RAYS   8192
#define P        256
#define HID      64
#define OUTW     261   // 3 rgb + depth + missed + 256 probs
#define FULL     0xffffffffu

__device__ __forceinline__ float4 f4add(float4 a, float4 b) {
    return make_float4(a.x + b.x, a.y + b.y, a.z + b.z, a.w + b.w);
}
__device__ __forceinline__ float4 shflup4(float4 v, int off) {
    return make_float4(__shfl_up_sync(FULL, v.x, off), __shfl_up_sync(FULL, v.y, off),
                       __shfl_up_sync(FULL, v.z, off), __shfl_up_sync(FULL, v.w, off));
}

// Per-warp scratch: prefix tables live through the sample loop; the probs
// staging buffer is only used afterwards, so it aliases the same storage.
union WarpScratch {
    struct { float4 TS[65]; float4 TD[65]; } t;   // 2080 B
    float pb[288];                                 // 1152 B (stride-9 staging)
};

__global__ __launch_bounds__(256, 5) void vr_kernel(
    const float* __restrict__ ray_start,   // [N,3]
    const float* __restrict__ ray_dir,     // [N,3]
    const float* __restrict__ depth,       // [N,P]
    const float* __restrict__ dists,       // [N,P]
    const int*   __restrict__ sidx,        // [N,P]
    const float* __restrict__ W1,          // [3,HID]
    const float* __restrict__ b1,          // [HID]
    const float* __restrict__ w_sigma,     // [HID]
    const float* __restrict__ W_rgb,       // [HID,3]
    const float* __restrict__ W_dir,       // [3,3]
    const float* __restrict__ b_rgb,       // [3]
    float*       __restrict__ out)         // [N,OUTW]
{
    __shared__ float s_ts[8][64];
    __shared__ WarpScratch ws[8];

    const int tid  = threadIdx.x;
    const int w    = tid >> 5;
    const int lane = tid & 31;
    const int ray  = blockIdx.x * 8 + w;

    // --- per-ray scalars ---
    const float rs0 = ray_start[ray * 3 + 0];
    const float rs1 = ray_start[ray * 3 + 1];
    const float rs2 = ray_start[ray * 3 + 2];
    const float rd0 = ray_dir[ray * 3 + 0];
    const float rd1 = ray_dir[ray * 3 + 1];
    const float rd2 = ray_dir[ray * 3 + 2];

    // --- per-unit setup: lane owns units uA=lane, uB=lane+32 ---
    float kA, kB;
    float4 sgSA, sgDA, sgSB, sgDB;
    float4 negS = make_float4(0.f, 0.f, 0.f, 0.f);
    float4 negD = make_float4(0.f, 0.f, 0.f, 0.f);

#pragma unroll
    for (int half = 0; half < 2; ++half) {
        const int u = lane + half * 32;
        const float w1x = W1[u], w1y = W1[HID + u], w1z = W1[2 * HID + u];
        const float S = b1[u] + rs0 * w1x + rs1 * w1y + rs2 * w1z;
        const float D = rd0 * w1x + rd1 * w1y + rd2 * w1z;
        const float wsg = w_sigma[u];
        const float wr0 = W_rgb[u * 3 + 0];
        const float wr1 = W_rgb[u * 3 + 1];
        const float wr2 = W_rgb[u * 3 + 2];
        float t;
        int isPos;
        if (D > 0.f)      { t = __fdividef(-S, D); isPos = 1; }
        else if (D < 0.f) { t = __fdividef(-S, D); isPos = 0; }
        else              { t = (S > 0.f) ? -1e30f : 1e30f; isPos = 1; }
        const float sgn = isPos ? 1.f : -1.f;
        float4 pS = make_float4(wsg * S, wr0 * S, wr1 * S, wr2 * S);
        float4 pD = make_float4(wsg * D, wr0 * D, wr1 * D, wr2 * D);
        if (!isPos) {
            negS = f4add(negS, pS);
            negD = f4add(negD, pD);
        }
        float4 gS = make_float4(sgn * pS.x, sgn * pS.y, sgn * pS.z, sgn * pS.w);
        float4 gD = make_float4(sgn * pD.x, sgn * pD.y, sgn * pD.z, sgn * pD.w);
        if (half == 0) { kA = t; sgSA = gS; sgDA = gD; }
        else           { kB = t; sgSB = gS; sgDB = gD; }
    }

    // --- warp reduction: neg-group totals (8 channels) ---
#pragma unroll
    for (int off = 16; off; off >>= 1) {
        negS.x += __shfl_xor_sync(FULL, negS.x, off);
        negS.y += __shfl_xor_sync(FULL, negS.y, off);
        negS.z += __shfl_xor_sync(FULL, negS.z, off);
        negS.w += __shfl_xor_sync(FULL, negS.w, off);
        negD.x += __shfl_xor_sync(FULL, negD.x, off);
        negD.y += __shfl_xor_sync(FULL, negD.y, off);
        negD.z += __shfl_xor_sync(FULL, negD.z, off);
        negD.w += __shfl_xor_sync(FULL, negD.w, off);
    }

    // --- counting rank (ties by id) ---
    int rA = 0, rB = 0;
#pragma unroll
    for (int src = 0; src < 32; ++src) {
        const float oA = __shfl_sync(FULL, kA, src);
        const float oB = __shfl_sync(FULL, kB, src);
        rA += (oA < kA) | ((oA == kA) & (src < lane));
        rA += (oB < kA);
        rB += (oA < kB) | (oA == kB);
        rB += (oB < kB) | ((oB == kB) & (src < lane));
    }

    // --- scatter signed payloads into sorted slots ---
    s_ts[w][rA] = kA;
    ws[w].t.TS[rA] = sgSA;
    ws[w].t.TD[rA] = sgDA;
    s_ts[w][rB] = kB;
    ws[w].t.TS[rB] = sgSB;
    ws[w].t.TD[rB] = sgDB;
    __syncwarp();

    // --- 8-channel exclusive scan over 64 slots, bake totN into base ---
    const int p0 = 2 * lane, p1 = p0 + 1;
    const float4 aS0 = ws[w].t.TS[p0], aS1 = ws[w].t.TS[p1];
    const float4 aD0 = ws[w].t.TD[p0], aD1 = ws[w].t.TD[p1];

    float4 iS = f4add(aS0, aS1);
    float4 iD = f4add(aD0, aD1);
#pragma unroll
    for (int off = 1; off < 32; off <<= 1) {
        float4 tS = shflup4(iS, off);
        float4 tD = shflup4(iD, off);
        if (lane >= off) {
            iS = f4add(iS, tS);
            iD = f4add(iD, tD);
        }
    }
    float4 eS = shflup4(iS, 1);
    float4 eD = shflup4(iD, 1);
    if (lane == 0) {
        eS = make_float4(0.f, 0.f, 0.f, 0.f);
        eD = make_float4(0.f, 0.f, 0.f, 0.f);
    }
    __syncwarp();
    const float4 b0S = f4add(negS, eS);
    const float4 b0D = f4add(negD, eD);
    ws[w].t.TS[p0] = b0S;  ws[w].t.TS[p1] = f4add(b0S, aS0);
    ws[w].t.TD[p0] = b0D;  ws[w].t.TD[p1] = f4add(b0D, aD0);
    if (lane == 31) {
        ws[w].t.TS[64] = f4add(negS, iS);
        ws[w].t.TD[64] = f4add(negD, iD);
    }
    __syncwarp();

    // --- load this lane's 8 contiguous samples ---
    const int base = ray * P + lane * 8;
    const float4 dA4 = *(const float4*)(depth + base);
    const float4 dB4 = *(const float4*)(depth + base + 4);
    const float dep[8] = {dA4.x, dA4.y, dA4.z, dA4.w, dB4.x, dB4.y, dB4.z, dB4.w};
    const float4 tA4 = *(const float4*)(dists + base);
    const float4 tB4 = *(const float4*)(dists + base + 4);
    const float dst7[8] = {tA4.x * 7.f, tA4.y * 7.f, tA4.z * 7.f, tA4.w * 7.f,
                           tB4.x * 7.f, tB4.y * 7.f, tB4.z * 7.f, tB4.w * 7.f};
    const int4 iA4 = *(const int4*)(sidx + base);
    const int4 iB4 = *(const int4*)(sidx + base + 4);
    const int idx[8] = {iA4.x, iA4.y, iA4.z, iA4.w, iB4.x, iB4.y, iB4.z, iB4.w};

    const float* ts = s_ts[w];

    // --- view-direction rgb bias ---
    const float dt0 = rd0 * W_dir[0] + rd1 * W_dir[3] + rd2 * W_dir[6] + b_rgb[0];
    const float dt1 = rd0 * W_dir[1] + rd1 * W_dir[4] + rd2 * W_dir[7] + b_rgb[1];
    const float dt2 = rd0 * W_dir[2] + rd1 * W_dir[5] + rd2 * W_dir[8] + b_rgb[2];

    // --- rank for first sample; cache next threshold in a register ---
    int c;
    {
        const float d = dep[0];
        if (ts[63] <= d) c = 64;
        else {
            c = 0;
            if (ts[c + 31] <= d) c += 32;
            if (ts[c + 15] <= d) c += 16;
            if (ts[c + 7]  <= d) c += 8;
            if (ts[c + 3]  <= d) c += 4;
            if (ts[c + 1]  <= d) c += 2;
            if (ts[c]      <= d) c += 1;
        }
    }
    float nxt = (c < 64) ? ts[c] : 3.4e38f;
    float4 TS = ws[w].t.TS[c];
    float4 TD = ws[w].t.TD[c];

    // --- fused per-sample loop ---
    float q[8];
    float qs = 0.f, qd = 0.f, qc0 = 0.f, qc1 = 0.f, qc2 = 0.f;
    float run = 1.f;
#pragma unroll
    for (int s = 0; s < 8; ++s) {
        const float d = dep[s];
        if (d >= nxt) {                       // rank moved (never true at s=0)
            do { ++c; } while (c < 64 && ts[c] <= d);
            nxt = (c < 64) ? ts[c] : 3.4e38f;
            TS = ws[w].t.TS[c];
            TD = ws[w].t.TD[c];
        }
        const float sigma = TS.x + d * TD.x;
        const float l0 = TS.y + d * TD.y;
        const float l1 = TS.z + d * TD.z;
        const float l2 = TS.w + d * TD.w;

        float fe = fmaxf(sigma, 0.f) * dst7[s];
        if (idx[s] == -1) fe = 0.f;
        const float es = __expf(-fe);
        const float qq = (1.f - es) * run;
        run *= es;
        q[s] = qq;

        qs += qq;
        qd += d * qq;
        const float r0 = __fdividef(1.f, 1.f + __expf(-(l0 + dt0)));
        const float r1 = __fdividef(1.f, 1.f + __expf(-(l1 + dt1)));
        const float r2 = __fdividef(1.f, 1.f + __expf(-(l2 + dt2)));
        qc0 += r0 * qq;
        qc1 += r1 * qq;
        qc2 += r2 * qq;
    }

    // --- warp multiplicative exclusive scan of lane products ---
    float incl = run;
#pragma unroll
    for (int off = 1; off < 32; off <<= 1) {
        float v = __shfl_up_sync(FULL, incl, off);
        if (lane >= off) incl *= v;
    }
    float excl = __shfl_up_sync(FULL, incl, 1);
    if (lane == 0) excl = 1.f;

    float psum = excl * qs;
    float dsum = excl * qd;
    float cs0  = excl * qc0;
    float cs1  = excl * qc1;
    float cs2  = excl * qc2;

    // --- probs staging in the ALIASED buffer (tables are dead now) ---
    __syncwarp();                  // all table reads complete before overwrite
    {
        float* pb = ws[w].pb;
        const int sb = lane * 9;
#pragma unroll
        for (int s = 0; s < 8; ++s) pb[sb + s] = excl * q[s];
        __syncwarp();
        float* orow = out + (long)ray * OUTW;
#pragma unroll
        for (int i = 0; i < 8; ++i) {
            const int m = i * 32 + lane;
            orow[5 + m] = pb[(m >> 3) * 9 + (m & 7)];
        }

#pragma unroll
        for (int off = 16; off; off >>= 1) {
            psum += __shfl_xor_sync(FULL, psum, off);
            dsum += __shfl_xor_sync(FULL, dsum, off);
            cs0  += __shfl_xor_sync(FULL, cs0, off);
            cs1  += __shfl_xor_sync(FULL, cs1, off);
            cs2  += __shfl_xor_sync(FULL, cs2, off);
        }
        if (lane == 0) {
            orow[0] = cs0;
            orow[1] = cs1;
            orow[2] = cs2;
            orow[3] = dsum;
            orow[4] = 1.f - psum;
        }
    }
}

extern "C" void kernel_launch(void* const* d_in, const int* in_sizes, int n_in,
                              void* d_out, int out_size) {
    const float* ray_start = (const float*)d_in[0];
    const float* ray_dir   = (const float*)d_in[1];
    const float* depth     = (const float*)d_in[2];
    const float* dists     = (const float*)d_in[3];
    const int*   sidx      = (const int*)d_in[4];
    const float* W1        = (const float*)d_in[5];
    const float* b1        = (const float*)d_in[6];
    const float* w_sigma   = (const float*)d_in[7];
    const float* W_rgb     = (const float*)d_in[8];
    const float* W_dir     = (const float*)d_in[9];
    const float* b_rgb     = (const float*)d_in[10];
    float* out = (float*)d_out;

    vr_kernel<<<N_RAYS / 8, 256>>>(ray_start, ray_dir, depth, dists, sidx,
                                   W1, b1, w_sigma, W_rgb, W_dir, b_rgb, out);
}